// round 11
// baseline (speedup 1.0000x reference)
#include <cuda_runtime.h>
#include <cstdint>

// Problem constants
#define Bn 16
#define Cn 256
#define Hn 128
#define Wn 128
#define HW 16384              // 2^14
#define HW4 4096
#define CHW4 1048576          // 2^20

// Geometry: 256 blocks x 512 threads; block owns one 64-px (half-row) tile/batch.
// Co-residency proven in R8 (2 blocks/SM x 148 SMs = 296 >= 256).
#define NBLK 256
#define NTHR 512
#define PX 64
#define PX4 16

// Globals
__device__ float    g_s[Bn * HW];        // channel sums, 1 MiB
__device__ unsigned g_flag[Bn * NBLK];   // per-(batch,tile) "s ready" flags

// ---------------------------------------------------------------------------
__global__ void reset_flags_kernel() {
    g_flag[blockIdx.x * blockDim.x + threadIdx.x] = 0u;
}

// ---------------------------------------------------------------------------
__global__ void __launch_bounds__(NTHR, 2)
fused_kernel(const float4* __restrict__ x,
             const float* __restrict__ f,
             float4* __restrict__ out) {
    __shared__ float4 aux[32 * PX4];     // [cg][px4] partial sums, 8 KiB
    __shared__ float4 x1s4[PX4];         // conv result for tile, 256 B
    float* x1s = (float*)x1s4;

    const int tid = threadIdx.x;
    const int t   = blockIdx.x;          // tile 0..255 (row = t>>1, half = t&1)
    const int px4 = tid & 15;            // float4-pixel within tile
    const int cg  = tid >> 4;            // channel group 0..31 (8 ch each)

    float fw[9];
#pragma unroll
    for (int k = 0; k < 9; ++k) fw[k] = f[k];

    for (int b = 0; b < Bn; ++b) {
        const size_t base = (size_t)b * CHW4 + (size_t)t * PX4 + px4;

        // ---- Phase 1: read x tile (DRAM) + partial channel sums ----
        float4 acc = make_float4(0.f, 0.f, 0.f, 0.f);
#pragma unroll
        for (int cc = 0; cc < 8; ++cc) {
            float4 v = x[base + (size_t)(cg * 8 + cc) * HW4];
            acc.x += v.x; acc.y += v.y; acc.z += v.z; acc.w += v.w;
        }
        aux[cg * PX4 + px4] = acc;
        __syncthreads();

        if (tid < PX4) {
            float4 a = make_float4(0.f, 0.f, 0.f, 0.f);
#pragma unroll
            for (int g = 0; g < 32; ++g) {
                float4 v = aux[g * PX4 + tid];
                a.x += v.x; a.y += v.y; a.z += v.z; a.w += v.w;
            }
            ((float4*)g_s)[(size_t)b * HW4 + t * PX4 + tid] = a;
        }
        __threadfence();                  // release s writes
        __syncthreads();
        if (tid == 0) atomicExch(&g_flag[b * NBLK + t], 1u);

        // ---- Acquire neighbor s tiles (rows r-1..r+1, both halves) ----
        {
            int r = t >> 1;
            if (tid < 6) {
                int rr = r - 1 + (tid >> 1);
                int nt = (rr << 1) + (tid & 1);
                if (rr >= 0 && rr < Hn && nt != t) {
                    unsigned* fl = &g_flag[b * NBLK + nt];
                    while (atomicAdd(fl, 0u) == 0u) __nanosleep(64);
                }
                __threadfence();          // acquire
            }
        }
        __syncthreads();

        // ---- Phase 2: conv3x3 (cross-corr, zero pad) on own tile ----
        if (tid < PX) {
            int p = t * PX + tid;         // pixel within batch
            int h = p >> 7;
            int w = p & (Wn - 1);
            const float* sb = g_s + b * HW;
            float a = 0.f;
#pragma unroll
            for (int di = 0; di < 3; ++di) {
                int hh = h + di - 1;
                if (hh < 0 || hh >= Hn) continue;
#pragma unroll
                for (int dj = 0; dj < 3; ++dj) {
                    int ww = w + dj - 1;
                    if (ww < 0 || ww >= Wn) continue;
                    a += sb[hh * Wn + ww] * fw[di * 3 + dj];
                }
            }
            x1s[tid] = a;
        }
        __syncthreads();

        // ---- Phase 3: re-read x tile (L2 hit) - x1, store out ----
        float4 bv = x1s4[px4];
#pragma unroll
        for (int cc = 0; cc < 8; ++cc) {
            size_t idx = base + (size_t)(cg * 8 + cc) * HW4;
            float4 v = x[idx];
            float4 o;
            o.x = v.x - bv.x; o.y = v.y - bv.y;
            o.z = v.z - bv.z; o.w = v.w - bv.w;
            out[idx] = o;
        }
        __syncthreads();                  // aux/x1s reuse next iteration
    }
}

// ---------------------------------------------------------------------------
extern "C" void kernel_launch(void* const* d_in, const int* in_sizes, int n_in,
                              void* d_out, int out_size) {
    const float* x = (const float*)d_in[0];   // (16,256,128,128) fp32
    const float* f = (const float*)d_in[1];   // (3,3) fp32
    float* out = (float*)d_out;

    reset_flags_kernel<<<(Bn * NBLK) / 256, 256>>>();
    fused_kernel<<<NBLK, NTHR>>>((const float4*)x, f, (float4*)out);
}